// round 9
// baseline (speedup 1.0000x reference)
#include <cuda_runtime.h>
#include <cuda_bf16.h>

// out[0,d,h,w,c] = in[0, z[d], row[h], col[w], 0]
// in (1,128,128,128,32) f32; z/row/col (64,) i32; out (1,64,64,64,32) f32.
//
// Split to keep the random gather reads (L2-set churn vs dirty output lines)
// out of the store kernel:
//   A: 8MB random gathers -> 1MB compact buffer. MLP=8/thread.
//   B: pure write stream, 4 independent coalesced streams/thread, reads L2-hit.
// Steady-state (graph replay): B's dirty lines stay in L2 (proven R7: DRAM=1.3%).

__device__ float g_compact[64 * 64 * 64];   // 1 MiB scratch

__global__ __launch_bounds__(256) void gather_kernel(
    const float* __restrict__ in,
    const int* __restrict__ zi,
    const int* __restrict__ ri,
    const int* __restrict__ ci)
{
    const int t = blockIdx.x * 256 + threadIdx.x;   // 0..32767
    #pragma unroll
    for (int k = 0; k < 8; k++) {
        const int pos = t + k * 32768;              // 8 independent positions
        const int w = pos & 63;
        const int h = (pos >> 6) & 63;
        const int d = pos >> 12;
        int src = (__ldg(zi + d) << 7) + __ldg(ri + h);   // z*128 + row
        src = ((src << 7) + __ldg(ci + w)) << 5;          // (*128 + col)*32
        g_compact[pos] = __ldg(in + src);
    }
}

__global__ __launch_bounds__(256) void broadcast_kernel(float4* __restrict__ out)
{
    const int gid = blockIdx.x * 256 + threadIdx.x;  // 0..524287
    float v[4];
    #pragma unroll
    for (int k = 0; k < 4; k++)
        v[k] = __ldg(&g_compact[(gid + k * 524288) >> 3]);   // L1/L2 hit
    #pragma unroll
    for (int k = 0; k < 4; k++)
        out[gid + k * 524288] = make_float4(v[k], v[k], v[k], v[k]);
}

extern "C" void kernel_launch(void* const* d_in, const int* in_sizes, int n_in,
                              void* d_out, int out_size)
{
    const float* in  = (const float*)d_in[0];
    const int*   zi  = (const int*)d_in[1];
    const int*   ri  = (const int*)d_in[2];
    const int*   ci  = (const int*)d_in[3];
    float4*      out = (float4*)d_out;

    // A: 262144 positions / 8 per thread = 32768 threads = 128 blocks
    gather_kernel<<<128, 256>>>(in, zi, ri, ci);
    // B: 2097152 float4s / 4 per thread = 524288 threads = 2048 blocks
    broadcast_kernel<<<2048, 256>>>(out);
}